// round 5
// baseline (speedup 1.0000x reference)
#include <cuda_runtime.h>
#include <math.h>

#define NN 8192
#define EE 262144
#define CC 64
#define NMASK (NN - 1)
#define ELLW 96

typedef unsigned long long u64;

// ---- static device scratch (zero-initialized at module load) ----
__device__ int   g_map[(size_t)NN * NN];   // LWW map: holds e+1 during a launch, reset by winners
__device__ int   g_rowcnt[NN];
__device__ float g_deg[NN];
__device__ float g_dinv[NN];
__device__ u64   g_ell[NN * ELLW];         // packed (w_bits<<32 | col)
__device__ float g_z[NN * CC];             // dinv * x
__device__ float g_tx1[NN * CC];
__device__ float g_zt[NN * CC];            // dinv * tx1
__device__ float g_sig;

// ---- packed fp32x2 helpers (ptxas won't emit FFMA2 from C++) ----
__device__ __forceinline__ void ffma2(u64& d, u64 a, u64 b) {
    asm("fma.rn.f32x2 %0, %1, %2, %0;" : "+l"(d) : "l"(a), "l"(b));
}
__device__ __forceinline__ u64 pack2(float x, float y) {
    u64 r; asm("mov.b64 %0, {%1, %2};" : "=l"(r) : "f"(x), "f"(y)); return r;
}
__device__ __forceinline__ u64 bcast2(float x) {
    u64 r; asm("mov.b64 %0, {%1, %1};" : "=l"(r) : "f"(x)); return r;
}

// ---- K1: fused init + mark max edge id per (row,col) ----
__global__ void k_pass1(const int* __restrict__ ei, const float* __restrict__ adaptive) {
    int e = blockIdx.x * blockDim.x + threadIdx.x;
    if (e < NN) { g_deg[e] = 1.0f; g_rowcnt[e] = 0; }
    if (e == 0) g_sig = 1.0f / (1.0f + expf(-adaptive[0]));
    if (e >= EE) return;
    int r = ei[e] & NMASK;
    int c = ei[EE + e] & NMASK;
    atomicMax(&g_map[r * NN + c], e + 1);
}

// ---- K2: winners -> ELL + degree; winner resets its map cell (race-free) ----
__global__ void k_pass2(const int* __restrict__ ei, const float* __restrict__ ew) {
    int e = blockIdx.x * blockDim.x + threadIdx.x;
    if (e >= EE) return;
    int r = ei[e] & NMASK;
    int c = ei[EE + e] & NMASK;
    int key = r * NN + c;
    if (g_map[key] == e + 1) {
        float aw = ew[e] * g_sig;
        int pos = atomicAdd(&g_rowcnt[r], 1);
        if (pos < ELLW) {
            u64 pk = ((u64)__float_as_uint(aw) << 32) | (u64)(unsigned)c;
            g_ell[r * ELLW + pos] = pk;
        }
        atomicAdd(&g_deg[r], aw);
        g_map[key] = 0;
    }
}

// ---- K3: dinv + z = dinv*x ----
__global__ void k_prep(const float* __restrict__ x) {
    int i = blockIdx.x * blockDim.x + threadIdx.x;
    if (i >= NN * 32) return;
    int row = i >> 5;
    float di = rsqrtf(g_deg[row]);
    float2 v = ((const float2*)x)[i];
    v.x *= di; v.y *= di;
    ((float2*)g_z)[i] = v;
    if ((i & 31) == 0) g_dinv[row] = di;
}

// ---- shared SpMM row body with MLP-4 unrolled gather ----
__device__ __forceinline__ float2 gather_row(const float2* __restrict__ z2,
                                             int row, int t) {
    float2 acc = z2[row * 32 + t];          // identity term (dinv*xin[row])
    int cnt = g_rowcnt[row]; if (cnt > ELLW) cnt = ELLW;
    const u64* ell = &g_ell[row * ELLW];
    int k = 0;
    for (; k + 4 <= cnt; k += 4) {
        u64 p0 = __ldg(&ell[k]);
        u64 p1 = __ldg(&ell[k + 1]);
        u64 p2 = __ldg(&ell[k + 2]);
        u64 p3 = __ldg(&ell[k + 3]);
        float2 c0 = z2[(int)(p0 & 0xffffffffu) * 32 + t];
        float2 c1 = z2[(int)(p1 & 0xffffffffu) * 32 + t];
        float2 c2 = z2[(int)(p2 & 0xffffffffu) * 32 + t];
        float2 c3 = z2[(int)(p3 & 0xffffffffu) * 32 + t];
        float w0 = __uint_as_float((unsigned)(p0 >> 32));
        float w1 = __uint_as_float((unsigned)(p1 >> 32));
        float w2 = __uint_as_float((unsigned)(p2 >> 32));
        float w3 = __uint_as_float((unsigned)(p3 >> 32));
        acc.x += w0 * c0.x; acc.y += w0 * c0.y;
        acc.x += w1 * c1.x; acc.y += w1 * c1.y;
        acc.x += w2 * c2.x; acc.y += w2 * c2.y;
        acc.x += w3 * c3.x; acc.y += w3 * c3.y;
    }
    for (; k < cnt; k++) {
        u64 pk = __ldg(&ell[k]);
        float2 zc = z2[(int)(pk & 0xffffffffu) * 32 + t];
        float w = __uint_as_float((unsigned)(pk >> 32));
        acc.x += w * zc.x; acc.y += w * zc.y;
    }
    return acc;
}

// ---- K4: tx1 = L @ x ; zt = dinv*tx1 ----
__global__ void __launch_bounds__(256) k_spmm1(const float* __restrict__ x) {
    int row = blockIdx.x * 8 + threadIdx.y;
    int t = threadIdx.x;
    float2 acc = gather_row((const float2*)g_z, row, t);
    float di = g_dinv[row];
    float2 xr = ((const float2*)x)[row * 32 + t];
    float2 y; y.x = xr.x - di * acc.x; y.y = xr.y - di * acc.y;
    ((float2*)g_tx1)[row * 32 + t] = y;
    float2 zt; zt.x = di * y.x; zt.y = di * y.y;
    ((float2*)g_zt)[row * 32 + t] = zt;
}

// ---- K5: tx2 (smem) = 2*(L@tx1) - x, then FFMA2 GEMM ----
extern __shared__ float s_dyn[];
__global__ void __launch_bounds__(256, 4) k_fuse(const float* __restrict__ x,
                                                 const float* __restrict__ W,
                                                 const float* __restrict__ bias,
                                                 float* __restrict__ out) {
    u64*   sW2  = (u64*)s_dyn;                 // 3*64*32 u64 = 48 KB, (w[t], w[t+32]) pairs
    float* stx2 = s_dyn + 3 * CC * 32 * 2;     // 32*64 floats = 8 KB
    int t = threadIdx.x, ty = threadIdx.y;     // t: 0..31, ty: 0..7
    int tid = ty * 32 + t;

    for (int i = tid; i < 3 * CC * 32; i += 256) {
        int m = i >> 11, rem = i & 2047;
        int c = rem >> 5, tt = rem & 31;
        const float* Wm = W + m * CC * CC + c * CC;
        sW2[i] = pack2(Wm[tt], Wm[tt + 32]);
    }

    int rbase = blockIdx.x * 32;
    const float2* zt2 = (const float2*)g_zt;
#pragma unroll
    for (int i = 0; i < 4; i++) {
        int lr = i * 8 + ty;
        int row = rbase + lr;
        float2 acc = gather_row(zt2, row, t);
        float di = g_dinv[row];
        float2 x1 = ((const float2*)g_tx1)[row * 32 + t];
        float2 x0 = ((const float2*)x)[row * 32 + t];
        stx2[lr * CC + 2 * t]     = 2.0f * (x1.x - di * acc.x) - x0.x;
        stx2[lr * CC + 2 * t + 1] = 2.0f * (x1.y - di * acc.y) - x0.y;
    }
    __syncthreads();

    u64 binit = pack2(bias[t], bias[t + 32]);
#pragma unroll
    for (int j = 0; j < 4; j++) {
        int lr = j * 8 + ty;
        int row = rbase + lr;
        u64 acc = binit;
        const float4* x4  = (const float4*)(x + row * CC);
        const float4* t14 = (const float4*)(g_tx1 + row * CC);
        const float4* t24 = (const float4*)(stx2 + lr * CC);
#pragma unroll
        for (int c4 = 0; c4 < 16; c4++) {
            float4 v0 = __ldg(&x4[c4]);
            float4 v1 = __ldg(&t14[c4]);
            float4 v2 = t24[c4];
            int cb = c4 * 4;
            const u64* w0 = &sW2[cb * 32 + t];
            const u64* w1 = &sW2[2048 + cb * 32 + t];
            const u64* w2 = &sW2[4096 + cb * 32 + t];
            ffma2(acc, bcast2(v0.x), w0[0]);
            ffma2(acc, bcast2(v1.x), w1[0]);
            ffma2(acc, bcast2(v2.x), w2[0]);
            ffma2(acc, bcast2(v0.y), w0[32]);
            ffma2(acc, bcast2(v1.y), w1[32]);
            ffma2(acc, bcast2(v2.y), w2[32]);
            ffma2(acc, bcast2(v0.z), w0[64]);
            ffma2(acc, bcast2(v1.z), w1[64]);
            ffma2(acc, bcast2(v2.z), w2[64]);
            ffma2(acc, bcast2(v0.w), w0[96]);
            ffma2(acc, bcast2(v1.w), w1[96]);
            ffma2(acc, bcast2(v2.w), w2[96]);
        }
        out[row * CC + t]      = __uint_as_float((unsigned)acc);
        out[row * CC + t + 32] = __uint_as_float((unsigned)(acc >> 32));
    }
}

extern "C" void kernel_launch(void* const* d_in, const int* in_sizes, int n_in,
                              void* d_out, int out_size) {
    const float* x        = (const float*)d_in[0];
    const int*   ei       = (const int*)d_in[1];
    const float* ew       = (const float*)d_in[2];
    const float* W        = (const float*)d_in[3];
    const float* adaptive = (const float*)d_in[4];
    const float* bias     = (const float*)d_in[5];
    float* out = (float*)d_out;

    const int fuse_smem = (3 * CC * 32 * 2 + 32 * CC) * sizeof(float);  // 56 KB
    cudaFuncSetAttribute(k_fuse, cudaFuncAttributeMaxDynamicSharedMemorySize, fuse_smem);

    k_pass1<<<EE / 256, 256>>>(ei, adaptive);
    k_pass2<<<EE / 256, 256>>>(ei, ew);
    k_prep<<<(NN * 32) / 256, 256>>>(x);
    k_spmm1<<<NN / 8, dim3(32, 8)>>>(x);
    k_fuse<<<NN / 32, dim3(32, 8), fuse_smem>>>(x, W, bias, out);
}

// round 6
// speedup vs baseline: 1.5560x; 1.5560x over previous
#include <cuda_runtime.h>
#include <math.h>

#define NN 8192
#define EE 262144
#define CC 64
#define NMASK (NN - 1)
#define ELLW 96

typedef unsigned long long u64;

// ---- static device scratch (zero-initialized at module load) ----
__device__ int   g_map[(size_t)NN * NN];   // LWW map: holds e+1 during a launch, reset by winners
__device__ int   g_rowcnt[NN];
__device__ float g_deg[NN];
__device__ float g_dinv[NN];
__device__ u64   g_ell[NN * ELLW];         // packed (w_bits<<32 | col); row stride 768B (16B aligned)
__device__ float g_z[NN * CC];             // dinv * x
__device__ float g_tx1[NN * CC];
__device__ float g_zt[NN * CC];            // dinv * tx1
__device__ float g_sig;

// ---- K1: fused init + mark max edge id per (row,col) ----
__global__ void k_pass1(const int* __restrict__ ei, const float* __restrict__ adaptive) {
    int e = blockIdx.x * blockDim.x + threadIdx.x;
    if (e < NN) { g_deg[e] = 1.0f; g_rowcnt[e] = 0; }
    if (e == 0) g_sig = 1.0f / (1.0f + expf(-adaptive[0]));
    if (e >= EE) return;
    int r = ei[e] & NMASK;
    int c = ei[EE + e] & NMASK;
    atomicMax(&g_map[r * NN + c], e + 1);
}

// ---- K2: winners -> ELL + degree; winner resets its map cell (race-free) ----
__global__ void k_pass2(const int* __restrict__ ei, const float* __restrict__ ew) {
    int e = blockIdx.x * blockDim.x + threadIdx.x;
    if (e >= EE) return;
    int r = ei[e] & NMASK;
    int c = ei[EE + e] & NMASK;
    int key = r * NN + c;
    if (g_map[key] == e + 1) {
        float aw = ew[e] * g_sig;
        int pos = atomicAdd(&g_rowcnt[r], 1);
        if (pos < ELLW) {
            u64 pk = ((u64)__float_as_uint(aw) << 32) | (u64)(unsigned)c;
            g_ell[r * ELLW + pos] = pk;
        }
        atomicAdd(&g_deg[r], aw);
        g_map[key] = 0;
    }
}

// ---- K3: dinv + z = dinv*x ----
__global__ void k_prep(const float* __restrict__ x) {
    int i = blockIdx.x * blockDim.x + threadIdx.x;
    if (i >= NN * 32) return;
    int row = i >> 5;
    float di = rsqrtf(g_deg[row]);
    float2 v = ((const float2*)x)[i];
    v.x *= di; v.y *= di;
    ((float2*)g_z)[i] = v;
    if ((i & 31) == 0) g_dinv[row] = di;
}

// ---- shared SpMM row body: MLP-8 gather, ELL via 4x LDG.128 ----
__device__ __forceinline__ float2 gather_row(const float2* __restrict__ z2,
                                             int row, int t) {
    float2 acc = z2[row * 32 + t];          // identity term (dinv*xin[row])
    int cnt = g_rowcnt[row]; if (cnt > ELLW) cnt = ELLW;
    const ulonglong2* ell2 = (const ulonglong2*)&g_ell[row * ELLW];
    int k = 0;
    for (; k + 8 <= cnt; k += 8) {
        ulonglong2 q0 = __ldg(&ell2[(k >> 1)]);
        ulonglong2 q1 = __ldg(&ell2[(k >> 1) + 1]);
        ulonglong2 q2 = __ldg(&ell2[(k >> 1) + 2]);
        ulonglong2 q3 = __ldg(&ell2[(k >> 1) + 3]);
        float2 c0 = z2[(int)(q0.x & 0xffffffffu) * 32 + t];
        float2 c1 = z2[(int)(q0.y & 0xffffffffu) * 32 + t];
        float2 c2 = z2[(int)(q1.x & 0xffffffffu) * 32 + t];
        float2 c3 = z2[(int)(q1.y & 0xffffffffu) * 32 + t];
        float2 c4 = z2[(int)(q2.x & 0xffffffffu) * 32 + t];
        float2 c5 = z2[(int)(q2.y & 0xffffffffu) * 32 + t];
        float2 c6 = z2[(int)(q3.x & 0xffffffffu) * 32 + t];
        float2 c7 = z2[(int)(q3.y & 0xffffffffu) * 32 + t];
        float w0 = __uint_as_float((unsigned)(q0.x >> 32));
        float w1 = __uint_as_float((unsigned)(q0.y >> 32));
        float w2 = __uint_as_float((unsigned)(q1.x >> 32));
        float w3 = __uint_as_float((unsigned)(q1.y >> 32));
        float w4 = __uint_as_float((unsigned)(q2.x >> 32));
        float w5 = __uint_as_float((unsigned)(q2.y >> 32));
        float w6 = __uint_as_float((unsigned)(q3.x >> 32));
        float w7 = __uint_as_float((unsigned)(q3.y >> 32));
        acc.x += w0 * c0.x; acc.y += w0 * c0.y;
        acc.x += w1 * c1.x; acc.y += w1 * c1.y;
        acc.x += w2 * c2.x; acc.y += w2 * c2.y;
        acc.x += w3 * c3.x; acc.y += w3 * c3.y;
        acc.x += w4 * c4.x; acc.y += w4 * c4.y;
        acc.x += w5 * c5.x; acc.y += w5 * c5.y;
        acc.x += w6 * c6.x; acc.y += w6 * c6.y;
        acc.x += w7 * c7.x; acc.y += w7 * c7.y;
    }
    for (; k < cnt; k++) {
        u64 pk = __ldg(&g_ell[row * ELLW + k]);
        float2 zc = z2[(int)(pk & 0xffffffffu) * 32 + t];
        float w = __uint_as_float((unsigned)(pk >> 32));
        acc.x += w * zc.x; acc.y += w * zc.y;
    }
    return acc;
}

// ---- K4: tx1 = L @ x ; zt = dinv*tx1 ----
__global__ void __launch_bounds__(256) k_spmm1(const float* __restrict__ x) {
    int row = blockIdx.x * 8 + threadIdx.y;
    int t = threadIdx.x;
    float2 acc = gather_row((const float2*)g_z, row, t);
    float di = g_dinv[row];
    float2 xr = ((const float2*)x)[row * 32 + t];
    float2 y; y.x = xr.x - di * acc.x; y.y = xr.y - di * acc.y;
    ((float2*)g_tx1)[row * 32 + t] = y;
    float2 zt; zt.x = di * y.x; zt.y = di * y.y;
    ((float2*)g_zt)[row * 32 + t] = zt;
}

// ---- K5: tx2 = 2*(L@tx1) - x (smem), then out = x@W0 + tx1@W1 + tx2@W2 + b ----
// (R4-proven structure: 72KB smem, scalar FFMA GEMM)
extern __shared__ float s_dyn[];
__global__ void k_fuse(const float* __restrict__ x,
                       const float* __restrict__ W,
                       const float* __restrict__ bias,
                       float* __restrict__ out) {
    float* sW   = s_dyn;                   // 3*64*64
    float* sx   = sW + 3 * CC * CC;        // 32*64
    float* stx1 = sx + 32 * CC;            // 32*64
    float* stx2 = stx1 + 32 * CC;          // 32*64
    int t = threadIdx.x, ty = threadIdx.y;
    int tid = ty * 32 + t;
    for (int i = tid; i < 3 * CC * CC; i += 256) sW[i] = W[i];

    int rbase = blockIdx.x * 32;
    const float2* zt2 = (const float2*)g_zt;
#pragma unroll
    for (int i = 0; i < 4; i++) {
        int lr = i * 8 + ty;
        int row = rbase + lr;
        float2 acc = gather_row(zt2, row, t);
        float di = g_dinv[row];
        float2 x1 = ((const float2*)g_tx1)[row * 32 + t];
        float2 x0 = ((const float2*)x)[row * 32 + t];
        float yx = x1.x - di * acc.x;
        float yy = x1.y - di * acc.y;
        sx[lr * CC + 2 * t]       = x0.x;  sx[lr * CC + 2 * t + 1]   = x0.y;
        stx1[lr * CC + 2 * t]     = x1.x;  stx1[lr * CC + 2 * t + 1] = x1.y;
        stx2[lr * CC + 2 * t]     = 2.0f * yx - x0.x;
        stx2[lr * CC + 2 * t + 1] = 2.0f * yy - x0.y;
    }
    __syncthreads();

    // GEMM phase: 64 out-channels via (t, t+32), 4 rows per (ty) thread
    float b0 = bias[t], b1 = bias[t + 32];
#pragma unroll
    for (int j = 0; j < 4; j++) {
        int lr = j * 8 + ty;
        int row = rbase + lr;
        float a0 = b0, a1 = b1;
#pragma unroll
        for (int c = 0; c < CC; c++) {
            float v0 = sx[lr * CC + c];
            float v1 = stx1[lr * CC + c];
            float v2 = stx2[lr * CC + c];
            a0 += v0 * sW[c * CC + t]      + v1 * sW[CC*CC + c * CC + t]      + v2 * sW[2*CC*CC + c * CC + t];
            a1 += v0 * sW[c * CC + t + 32] + v1 * sW[CC*CC + c * CC + t + 32] + v2 * sW[2*CC*CC + c * CC + t + 32];
        }
        out[row * CC + t]      = a0;
        out[row * CC + t + 32] = a1;
    }
}

extern "C" void kernel_launch(void* const* d_in, const int* in_sizes, int n_in,
                              void* d_out, int out_size) {
    const float* x        = (const float*)d_in[0];
    const int*   ei       = (const int*)d_in[1];
    const float* ew       = (const float*)d_in[2];
    const float* W        = (const float*)d_in[3];
    const float* adaptive = (const float*)d_in[4];
    const float* bias     = (const float*)d_in[5];
    float* out = (float*)d_out;

    const int fuse_smem = (3 * CC * CC + 3 * 32 * CC) * sizeof(float);  // 72 KB
    cudaFuncSetAttribute(k_fuse, cudaFuncAttributeMaxDynamicSharedMemorySize, fuse_smem);

    k_pass1<<<EE / 256, 256>>>(ei, adaptive);
    k_pass2<<<EE / 256, 256>>>(ei, ew);
    k_prep<<<(NN * 32) / 256, 256>>>(x);
    k_spmm1<<<NN / 8, dim3(32, 8)>>>(x);
    k_fuse<<<NN / 32, dim3(32, 8), fuse_smem>>>(x, W, bias, out);
}

// round 7
// speedup vs baseline: 1.5953x; 1.0252x over previous
#include <cuda_runtime.h>
#include <math.h>

#define NN 8192
#define EE 262144
#define CC 64
#define NMASK (NN - 1)
#define ELLW 96
#define HBITS 20
#define HSIZE (1 << HBITS)
#define HMASK (HSIZE - 1)

typedef unsigned long long u64;

// ---- static device scratch (zero-initialized at module load) ----
__device__ u64   g_hash[HSIZE];            // 8 MB open-addressed LWW table (L2-resident)
__device__ int   g_slotrec[EE];            // slot touched by each edge (for clean)
__device__ int   g_rowcnt[NN];
__device__ float g_deg[NN];                // accumulated edge weight (identity added in prep)
__device__ float g_dinv[NN];
__device__ u64   g_ell[NN * ELLW];         // packed (w_bits<<32 | col); row stride 768B
__device__ float g_z[NN * CC];             // dinv * x
__device__ float g_tx1[NN * CC];
__device__ float g_zt[NN * CC];            // dinv * tx1

__device__ __forceinline__ void add_entry(int r, int c, float w) {
    int pos = atomicAdd(&g_rowcnt[r], 1);
    if (pos < ELLW) {
        u64 pk = ((u64)__float_as_uint(w) << 32) | (u64)(unsigned)c;
        g_ell[r * ELLW + pos] = pk;
    }
    atomicAdd(&g_deg[r], w);
}

// ---- K1: single-pass dedup + ELL build via L2-resident hash ----
// Slot value: ((key+1)<<32)|(e+1). Same-key max == max edge id (LWW).
// Every displacement subtracts the displaced edge's weight, so the per-(r,c)
// net sum equals the final winner's weight regardless of interleaving.
__global__ void k_build(const int* __restrict__ ei, const float* __restrict__ ew,
                        const float* __restrict__ adaptive) {
    int e = blockIdx.x * blockDim.x + threadIdx.x;
    if (e >= EE) return;
    float sig = 1.0f / (1.0f + expf(-adaptive[0]));
    int r = ei[e] & NMASK;
    int c = ei[EE + e] & NMASK;
    unsigned key = (unsigned)(r * NN + c);          // < 2^26
    u64 desired = ((u64)(key + 1) << 32) | (u64)(unsigned)(e + 1);
    unsigned slot = (key * 2654435761u) >> (32 - HBITS);
    float aw = ew[e] * sig;
    while (true) {
        u64 old = atomicCAS(&g_hash[slot], 0ULL, desired);
        if (old == 0ULL) {                          // inserted fresh
            add_entry(r, c, aw);
            g_slotrec[e] = (int)slot;
            break;
        }
        if ((unsigned)(old >> 32) == key + 1) {     // same (r,c)
            if ((unsigned)old < (unsigned)(e + 1)) {
                u64 prev = atomicMax(&g_hash[slot], desired);
                if ((unsigned)prev < (unsigned)(e + 1)) {
                    int eprev = (int)(unsigned)prev - 1;   // displaced provisional winner
                    add_entry(r, c, aw);
                    add_entry(r, c, -(ew[eprev] * sig));
                }
            }
            g_slotrec[e] = (int)slot;
            break;
        }
        slot = (slot + 1) & HMASK;                  // different key: probe on
    }
}

// ---- K2: dinv = (1+deg)^-1/2 ; z = dinv*x ----
__global__ void k_prep(const float* __restrict__ x) {
    int i = blockIdx.x * blockDim.x + threadIdx.x;
    if (i >= NN * 32) return;
    int row = i >> 5;
    float di = rsqrtf(1.0f + g_deg[row]);
    float2 v = ((const float2*)x)[i];
    v.x *= di; v.y *= di;
    ((float2*)g_z)[i] = v;
    if ((i & 31) == 0) g_dinv[row] = di;
}

// ---- shared SpMM row body: MLP-8 gather, ELL via 4x LDG.128 ----
__device__ __forceinline__ float2 gather_row(const float2* __restrict__ z2,
                                             int row, int t) {
    float2 acc = z2[row * 32 + t];          // identity term (dinv*xin[row])
    int cnt = g_rowcnt[row]; if (cnt > ELLW) cnt = ELLW;
    const ulonglong2* ell2 = (const ulonglong2*)&g_ell[row * ELLW];
    int k = 0;
    for (; k + 8 <= cnt; k += 8) {
        ulonglong2 q0 = __ldg(&ell2[(k >> 1)]);
        ulonglong2 q1 = __ldg(&ell2[(k >> 1) + 1]);
        ulonglong2 q2 = __ldg(&ell2[(k >> 1) + 2]);
        ulonglong2 q3 = __ldg(&ell2[(k >> 1) + 3]);
        float2 c0 = z2[(int)(q0.x & 0xffffffffu) * 32 + t];
        float2 c1 = z2[(int)(q0.y & 0xffffffffu) * 32 + t];
        float2 c2 = z2[(int)(q1.x & 0xffffffffu) * 32 + t];
        float2 c3 = z2[(int)(q1.y & 0xffffffffu) * 32 + t];
        float2 c4 = z2[(int)(q2.x & 0xffffffffu) * 32 + t];
        float2 c5 = z2[(int)(q2.y & 0xffffffffu) * 32 + t];
        float2 c6 = z2[(int)(q3.x & 0xffffffffu) * 32 + t];
        float2 c7 = z2[(int)(q3.y & 0xffffffffu) * 32 + t];
        float w0 = __uint_as_float((unsigned)(q0.x >> 32));
        float w1 = __uint_as_float((unsigned)(q0.y >> 32));
        float w2 = __uint_as_float((unsigned)(q1.x >> 32));
        float w3 = __uint_as_float((unsigned)(q1.y >> 32));
        float w4 = __uint_as_float((unsigned)(q2.x >> 32));
        float w5 = __uint_as_float((unsigned)(q2.y >> 32));
        float w6 = __uint_as_float((unsigned)(q3.x >> 32));
        float w7 = __uint_as_float((unsigned)(q3.y >> 32));
        acc.x += w0 * c0.x; acc.y += w0 * c0.y;
        acc.x += w1 * c1.x; acc.y += w1 * c1.y;
        acc.x += w2 * c2.x; acc.y += w2 * c2.y;
        acc.x += w3 * c3.x; acc.y += w3 * c3.y;
        acc.x += w4 * c4.x; acc.y += w4 * c4.y;
        acc.x += w5 * c5.x; acc.y += w5 * c5.y;
        acc.x += w6 * c6.x; acc.y += w6 * c6.y;
        acc.x += w7 * c7.x; acc.y += w7 * c7.y;
    }
    for (; k < cnt; k++) {
        u64 pk = __ldg(&g_ell[row * ELLW + k]);
        float2 zc = z2[(int)(pk & 0xffffffffu) * 32 + t];
        float w = __uint_as_float((unsigned)(pk >> 32));
        acc.x += w * zc.x; acc.y += w * zc.y;
    }
    return acc;
}

// ---- K3: tx1 = L @ x ; zt = dinv*tx1 ----
__global__ void __launch_bounds__(256) k_spmm1(const float* __restrict__ x) {
    int row = blockIdx.x * 8 + threadIdx.y;
    int t = threadIdx.x;
    float2 acc = gather_row((const float2*)g_z, row, t);
    float di = g_dinv[row];
    float2 xr = ((const float2*)x)[row * 32 + t];
    float2 y; y.x = xr.x - di * acc.x; y.y = xr.y - di * acc.y;
    ((float2*)g_tx1)[row * 32 + t] = y;
    float2 zt; zt.x = di * y.x; zt.y = di * y.y;
    ((float2*)g_zt)[row * 32 + t] = zt;
}

// ---- K4: tx2 = 2*(L@tx1) - x (smem), then out = x@W0 + tx1@W1 + tx2@W2 + b ----
extern __shared__ float s_dyn[];
__global__ void k_fuse(const float* __restrict__ x,
                       const float* __restrict__ W,
                       const float* __restrict__ bias,
                       float* __restrict__ out) {
    float* sW   = s_dyn;                   // 3*64*64
    float* sx   = sW + 3 * CC * CC;        // 32*64
    float* stx1 = sx + 32 * CC;            // 32*64
    float* stx2 = stx1 + 32 * CC;          // 32*64
    int t = threadIdx.x, ty = threadIdx.y;
    int tid = ty * 32 + t;
    for (int i = tid; i < 3 * CC * CC; i += 256) sW[i] = W[i];

    int rbase = blockIdx.x * 32;
    const float2* zt2 = (const float2*)g_zt;
#pragma unroll
    for (int i = 0; i < 4; i++) {
        int lr = i * 8 + ty;
        int row = rbase + lr;
        float2 acc = gather_row(zt2, row, t);
        float di = g_dinv[row];
        float2 x1 = ((const float2*)g_tx1)[row * 32 + t];
        float2 x0 = ((const float2*)x)[row * 32 + t];
        float yx = x1.x - di * acc.x;
        float yy = x1.y - di * acc.y;
        sx[lr * CC + 2 * t]       = x0.x;  sx[lr * CC + 2 * t + 1]   = x0.y;
        stx1[lr * CC + 2 * t]     = x1.x;  stx1[lr * CC + 2 * t + 1] = x1.y;
        stx2[lr * CC + 2 * t]     = 2.0f * yx - x0.x;
        stx2[lr * CC + 2 * t + 1] = 2.0f * yy - x0.y;
    }
    __syncthreads();

    float b0 = bias[t], b1 = bias[t + 32];
#pragma unroll
    for (int j = 0; j < 4; j++) {
        int lr = j * 8 + ty;
        int row = rbase + lr;
        float a0 = b0, a1 = b1;
#pragma unroll
        for (int c = 0; c < CC; c++) {
            float v0 = sx[lr * CC + c];
            float v1 = stx1[lr * CC + c];
            float v2 = stx2[lr * CC + c];
            a0 += v0 * sW[c * CC + t]      + v1 * sW[CC*CC + c * CC + t]      + v2 * sW[2*CC*CC + c * CC + t];
            a1 += v0 * sW[c * CC + t + 32] + v1 * sW[CC*CC + c * CC + t + 32] + v2 * sW[2*CC*CC + c * CC + t + 32];
        }
        out[row * CC + t]      = a0;
        out[row * CC + t + 32] = a1;
    }
}

// ---- K5: clean touched hash slots + per-row counters for next replay ----
__global__ void k_clean() {
    int i = blockIdx.x * blockDim.x + threadIdx.x;
    if (i < NN) { g_deg[i] = 0.0f; g_rowcnt[i] = 0; }
    if (i < EE) g_hash[g_slotrec[i]] = 0ULL;   // dup writes to same slot are fine
}

extern "C" void kernel_launch(void* const* d_in, const int* in_sizes, int n_in,
                              void* d_out, int out_size) {
    const float* x        = (const float*)d_in[0];
    const int*   ei       = (const int*)d_in[1];
    const float* ew       = (const float*)d_in[2];
    const float* W        = (const float*)d_in[3];
    const float* adaptive = (const float*)d_in[4];
    const float* bias     = (const float*)d_in[5];
    float* out = (float*)d_out;

    const int fuse_smem = (3 * CC * CC + 3 * 32 * CC) * sizeof(float);  // 72 KB
    cudaFuncSetAttribute(k_fuse, cudaFuncAttributeMaxDynamicSharedMemorySize, fuse_smem);

    k_build<<<EE / 256, 256>>>(ei, ew, adaptive);
    k_prep<<<(NN * 32) / 256, 256>>>(x);
    k_spmm1<<<NN / 8, dim3(32, 8)>>>(x);
    k_fuse<<<NN / 32, dim3(32, 8), fuse_smem>>>(x, W, bias, out);
    k_clean<<<EE / 256, 256>>>();
}

// round 8
// speedup vs baseline: 1.8969x; 1.1891x over previous
#include <cuda_runtime.h>
#include <math.h>

#define NN 8192
#define EE 262144
#define CC 64
#define NMASK (NN - 1)
#define ELLW 96
#define HBITS 20
#define HSIZE (1 << HBITS)
#define HMASK (HSIZE - 1)
#define WP 68   // padded W column stride (16B aligned, conflict-free LDS.128)

typedef unsigned long long u64;

// ---- static device scratch (zero-initialized at module load) ----
__device__ u64   g_hash[HSIZE];            // 8 MB open-addressed LWW table (L2-resident)
__device__ int   g_slotrec[EE];            // slot touched by each edge (for clean)
__device__ int   g_rowcnt[NN];
__device__ float g_deg[NN];                // accumulated edge weight (identity added in prep)
__device__ float g_dinv[NN];
__device__ u64   g_ell[NN * ELLW];         // packed (w_bits<<32 | col); row stride 768B
__device__ float g_z[NN * CC];             // dinv * x
__device__ float g_tx1[NN * CC];
__device__ float g_zt[NN * CC];            // dinv * tx1
__device__ float g_tx2[NN * CC];

__device__ __forceinline__ void add_entry(int r, int c, float w) {
    int pos = atomicAdd(&g_rowcnt[r], 1);
    if (pos < ELLW) {
        u64 pk = ((u64)__float_as_uint(w) << 32) | (u64)(unsigned)c;
        g_ell[r * ELLW + pos] = pk;
    }
    atomicAdd(&g_deg[r], w);
}

// ---- K1: single-pass dedup + ELL build via L2-resident hash ----
__global__ void k_build(const int* __restrict__ ei, const float* __restrict__ ew,
                        const float* __restrict__ adaptive) {
    int e = blockIdx.x * blockDim.x + threadIdx.x;
    if (e >= EE) return;
    float sig = 1.0f / (1.0f + expf(-adaptive[0]));
    int r = ei[e] & NMASK;
    int c = ei[EE + e] & NMASK;
    unsigned key = (unsigned)(r * NN + c);          // < 2^26
    u64 desired = ((u64)(key + 1) << 32) | (u64)(unsigned)(e + 1);
    unsigned slot = (key * 2654435761u) >> (32 - HBITS);
    float aw = ew[e] * sig;
    while (true) {
        u64 old = atomicCAS(&g_hash[slot], 0ULL, desired);
        if (old == 0ULL) {
            add_entry(r, c, aw);
            g_slotrec[e] = (int)slot;
            break;
        }
        if ((unsigned)(old >> 32) == key + 1) {
            if ((unsigned)old < (unsigned)(e + 1)) {
                u64 prev = atomicMax(&g_hash[slot], desired);
                if ((unsigned)prev < (unsigned)(e + 1)) {
                    int eprev = (int)(unsigned)prev - 1;
                    add_entry(r, c, aw);
                    add_entry(r, c, -(ew[eprev] * sig));
                }
            }
            g_slotrec[e] = (int)slot;
            break;
        }
        slot = (slot + 1) & HMASK;
    }
}

// ---- K2: dinv = (1+deg)^-1/2 ; z = dinv*x ----
__global__ void k_prep(const float* __restrict__ x) {
    int i = blockIdx.x * blockDim.x + threadIdx.x;
    if (i >= NN * 32) return;
    int row = i >> 5;
    float di = rsqrtf(1.0f + g_deg[row]);
    float2 v = ((const float2*)x)[i];
    v.x *= di; v.y *= di;
    ((float2*)g_z)[i] = v;
    if ((i & 31) == 0) g_dinv[row] = di;
}

// ---- shared SpMM row body: MLP-8 gather, ELL via 4x LDG.128 ----
__device__ __forceinline__ float2 gather_row(const float2* __restrict__ z2,
                                             int row, int t) {
    float2 acc = z2[row * 32 + t];          // identity term (dinv*xin[row])
    int cnt = g_rowcnt[row]; if (cnt > ELLW) cnt = ELLW;
    const ulonglong2* ell2 = (const ulonglong2*)&g_ell[row * ELLW];
    int k = 0;
    for (; k + 8 <= cnt; k += 8) {
        ulonglong2 q0 = __ldg(&ell2[(k >> 1)]);
        ulonglong2 q1 = __ldg(&ell2[(k >> 1) + 1]);
        ulonglong2 q2 = __ldg(&ell2[(k >> 1) + 2]);
        ulonglong2 q3 = __ldg(&ell2[(k >> 1) + 3]);
        float2 c0 = z2[(int)(q0.x & 0xffffffffu) * 32 + t];
        float2 c1 = z2[(int)(q0.y & 0xffffffffu) * 32 + t];
        float2 c2 = z2[(int)(q1.x & 0xffffffffu) * 32 + t];
        float2 c3 = z2[(int)(q1.y & 0xffffffffu) * 32 + t];
        float2 c4 = z2[(int)(q2.x & 0xffffffffu) * 32 + t];
        float2 c5 = z2[(int)(q2.y & 0xffffffffu) * 32 + t];
        float2 c6 = z2[(int)(q3.x & 0xffffffffu) * 32 + t];
        float2 c7 = z2[(int)(q3.y & 0xffffffffu) * 32 + t];
        float w0 = __uint_as_float((unsigned)(q0.x >> 32));
        float w1 = __uint_as_float((unsigned)(q0.y >> 32));
        float w2 = __uint_as_float((unsigned)(q1.x >> 32));
        float w3 = __uint_as_float((unsigned)(q1.y >> 32));
        float w4 = __uint_as_float((unsigned)(q2.x >> 32));
        float w5 = __uint_as_float((unsigned)(q2.y >> 32));
        float w6 = __uint_as_float((unsigned)(q3.x >> 32));
        float w7 = __uint_as_float((unsigned)(q3.y >> 32));
        acc.x += w0 * c0.x; acc.y += w0 * c0.y;
        acc.x += w1 * c1.x; acc.y += w1 * c1.y;
        acc.x += w2 * c2.x; acc.y += w2 * c2.y;
        acc.x += w3 * c3.x; acc.y += w3 * c3.y;
        acc.x += w4 * c4.x; acc.y += w4 * c4.y;
        acc.x += w5 * c5.x; acc.y += w5 * c5.y;
        acc.x += w6 * c6.x; acc.y += w6 * c6.y;
        acc.x += w7 * c7.x; acc.y += w7 * c7.y;
    }
    for (; k < cnt; k++) {
        u64 pk = __ldg(&g_ell[row * ELLW + k]);
        float2 zc = z2[(int)(pk & 0xffffffffu) * 32 + t];
        float w = __uint_as_float((unsigned)(pk >> 32));
        acc.x += w * zc.x; acc.y += w * zc.y;
    }
    return acc;
}

// ---- K3: tx1 = L @ x ; zt = dinv*tx1 ----
__global__ void __launch_bounds__(256) k_spmm1(const float* __restrict__ x) {
    int row = blockIdx.x * 8 + threadIdx.y;
    int t = threadIdx.x;
    float2 acc = gather_row((const float2*)g_z, row, t);
    float di = g_dinv[row];
    float2 xr = ((const float2*)x)[row * 32 + t];
    float2 y; y.x = xr.x - di * acc.x; y.y = xr.y - di * acc.y;
    ((float2*)g_tx1)[row * 32 + t] = y;
    float2 zt; zt.x = di * y.x; zt.y = di * y.y;
    ((float2*)g_zt)[row * 32 + t] = zt;
}

// ---- K4: tx2 = 2*(L @ tx1) - x ----
__global__ void __launch_bounds__(256) k_spmm2(const float* __restrict__ x) {
    int row = blockIdx.x * 8 + threadIdx.y;
    int t = threadIdx.x;
    float2 acc = gather_row((const float2*)g_zt, row, t);
    float di = g_dinv[row];
    float2 x1 = ((const float2*)g_tx1)[row * 32 + t];
    float2 x0 = ((const float2*)x)[row * 32 + t];
    float2 y;
    y.x = 2.0f * (x1.x - di * acc.x) - x0.x;
    y.y = 2.0f * (x1.y - di * acc.y) - x0.y;
    ((float2*)g_tx2)[row * 32 + t] = y;
}

// ---- K5: out = x@W0 + tx1@W1 + tx2@W2 + bias ----
// W transposed in smem: sWt[m][o*WP + c], WP=68 -> 16B aligned rows,
// lanes o hit banks (4o+c)%32 within an 8-lane phase: conflict-free LDS.128.
extern __shared__ float s_dyn[];
__global__ void __launch_bounds__(256) k_gemm(const float* __restrict__ x,
                                              const float* __restrict__ W,
                                              const float* __restrict__ bias,
                                              float* __restrict__ out) {
    float* sWt = s_dyn;                     // 3 * 64 * WP floats ~= 51 KB
    int o = threadIdx.x;                    // 0..63 out channel
    int ty = threadIdx.y;                   // 0..3
    int tid = ty * 64 + o;
    for (int i = tid; i < 3 * CC * CC; i += 256) {
        int m = i >> 12;                    // /4096
        int rem = i & 4095;
        int c = rem >> 6, oo = rem & 63;
        sWt[(m * CC + oo) * WP + c] = W[i];
    }
    __syncthreads();

    const float* w0 = &sWt[(0 * CC + o) * WP];
    const float* w1 = &sWt[(1 * CC + o) * WP];
    const float* w2 = &sWt[(2 * CC + o) * WP];
    int rbase = blockIdx.x * 32;
    float b = bias[o];
#pragma unroll
    for (int j = 0; j < 8; j++) {
        int row = rbase + j * 4 + ty;
        const float4* x4  = (const float4*)(x + row * CC);
        const float4* t14 = (const float4*)(g_tx1 + row * CC);
        const float4* t24 = (const float4*)(g_tx2 + row * CC);
        float a = b;
#pragma unroll
        for (int c4 = 0; c4 < 16; c4++) {
            float4 v0 = __ldg(&x4[c4]);
            float4 v1 = __ldg(&t14[c4]);
            float4 v2 = __ldg(&t24[c4]);
            float4 u0 = *(const float4*)&w0[c4 * 4];
            float4 u1 = *(const float4*)&w1[c4 * 4];
            float4 u2 = *(const float4*)&w2[c4 * 4];
            a += v0.x * u0.x + v0.y * u0.y + v0.z * u0.z + v0.w * u0.w;
            a += v1.x * u1.x + v1.y * u1.y + v1.z * u1.z + v1.w * u1.w;
            a += v2.x * u2.x + v2.y * u2.y + v2.z * u2.z + v2.w * u2.w;
        }
        out[row * CC + o] = a;
    }
}

// ---- K6: clean touched hash slots + per-row counters for next replay ----
__global__ void k_clean() {
    int i = blockIdx.x * blockDim.x + threadIdx.x;
    if (i < NN) { g_deg[i] = 0.0f; g_rowcnt[i] = 0; }
    if (i < EE) g_hash[g_slotrec[i]] = 0ULL;
}

extern "C" void kernel_launch(void* const* d_in, const int* in_sizes, int n_in,
                              void* d_out, int out_size) {
    const float* x        = (const float*)d_in[0];
    const int*   ei       = (const int*)d_in[1];
    const float* ew       = (const float*)d_in[2];
    const float* W        = (const float*)d_in[3];
    const float* adaptive = (const float*)d_in[4];
    const float* bias     = (const float*)d_in[5];
    float* out = (float*)d_out;

    const int gemm_smem = 3 * CC * WP * sizeof(float);   // ~51 KB
    cudaFuncSetAttribute(k_gemm, cudaFuncAttributeMaxDynamicSharedMemorySize, gemm_smem);

    k_build<<<EE / 256, 256>>>(ei, ew, adaptive);
    k_prep<<<(NN * 32) / 256, 256>>>(x);
    k_spmm1<<<NN / 8, dim3(32, 8)>>>(x);
    k_spmm2<<<NN / 8, dim3(32, 8)>>>(x);
    k_gemm<<<NN / 32, dim3(64, 4), gemm_smem>>>(x, W, bias, out);
    k_clean<<<EE / 256, 256>>>();
}